// round 13
// baseline (speedup 1.0000x reference)
#include <cuda_runtime.h>
#include <cuda_bf16.h>
#include <cstdint>

#define NB 256   // batch

// ---------------- scratch (device globals; no allocation) ----------------
__device__ float g_h1n [(size_t)NB*32*32*32];   // NHWC
__device__ float g_off2[(size_t)NB*16*16*18];   // position-major (b,hw,18)
__device__ float g_h2n [(size_t)NB*64*16*16];
__device__ float g_off3[(size_t)NB*16*16*18];
__device__ float g_h3n [(size_t)NB*128*16*16];
__device__ float g_off4[(size_t)NB*8*8*18];
__device__ float g_h4n [(size_t)NB*128*8*8];
__device__ __nv_bfloat16 g_wth2[64*288],  g_wtl2[64*288];    // deform weights [k][O]
__device__ __nv_bfloat16 g_wth3[128*576], g_wtl3[128*576];
__device__ __nv_bfloat16 g_wth4[128*1152],g_wtl4[128*1152];
__device__ __nv_bfloat16 g_wph2[288*40],  g_wpl2[288*40];    // offset weights [k][40]
__device__ __nv_bfloat16 g_wph3[576*40],  g_wpl3[576*40];
__device__ __nv_bfloat16 g_wph4[1152*40], g_wpl4[1152*40];

// ---------------- small asm helpers ----------------
__device__ __forceinline__ unsigned long long pk2(float lo, float hi) {
    unsigned long long r;
    asm("mov.b64 %0, {%1, %2};" : "=l"(r) : "f"(lo), "f"(hi));
    return r;
}
__device__ __forceinline__ void fma2(unsigned long long& d,
                                     unsigned long long a, unsigned long long b) {
    asm("fma.rn.f32x2 %0, %1, %2, %0;" : "+l"(d) : "l"(a), "l"(b));
}
__device__ __forceinline__ float2 upk2(unsigned long long v) {
    float2 r;
    asm("mov.b64 {%0, %1}, %2;" : "=f"(r.x), "=f"(r.y) : "l"(v));
    return r;
}
__device__ __forceinline__ uint32_t cvt_bf16x2(float hi, float lo) {
    uint32_t r;
    asm("cvt.rn.bf16x2.f32 %0, %1, %2;" : "=r"(r) : "f"(hi), "f"(lo));
    return r;
}
__device__ __forceinline__ uint32_t sptr(const void* p) {
    return (uint32_t)__cvta_generic_to_shared(p);
}
__device__ __forceinline__ void cpa16(uint32_t dst, const void* src) {
    asm volatile("cp.async.cg.shared.global [%0], [%1], 16;"
                 :: "r"(dst), "l"(src) : "memory");
}
__device__ __forceinline__ void cpa_commit() {
    asm volatile("cp.async.commit_group;" ::: "memory");
}
__device__ __forceinline__ void cpa_wait0() {
    asm volatile("cp.async.wait_group 0;" ::: "memory");
}
__device__ __forceinline__ void ldsm4(uint32_t& r0, uint32_t& r1, uint32_t& r2,
                                      uint32_t& r3, uint32_t addr) {
    asm volatile("ldmatrix.sync.aligned.m8n8.x4.shared.b16 {%0,%1,%2,%3},[%4];"
                 : "=r"(r0), "=r"(r1), "=r"(r2), "=r"(r3) : "r"(addr));
}
__device__ __forceinline__ void ldsm4t(uint32_t& r0, uint32_t& r1, uint32_t& r2,
                                       uint32_t& r3, uint32_t addr) {
    asm volatile("ldmatrix.sync.aligned.m8n8.x4.trans.shared.b16 {%0,%1,%2,%3},[%4];"
                 : "=r"(r0), "=r"(r1), "=r"(r2), "=r"(r3) : "r"(addr));
}
__device__ __forceinline__ void mma16816(float* d, const uint32_t* a,
                                         uint32_t b0, uint32_t b1) {
    asm volatile(
        "mma.sync.aligned.m16n8k16.row.col.f32.bf16.bf16.f32 "
        "{%0,%1,%2,%3},{%4,%5,%6,%7},{%8,%9},{%0,%1,%2,%3};"
        : "+f"(d[0]), "+f"(d[1]), "+f"(d[2]), "+f"(d[3])
        : "r"(a[0]), "r"(a[1]), "r"(a[2]), "r"(a[3]), "r"(b0), "r"(b1));
}
// split 4 f32 into bf16 hi/lo planes and store (2x uint2)
__device__ __forceinline__ void split4_store(uint32_t* xh, uint32_t* xl, int idx,
                                             float2 v01, float2 v23) {
    uint32_t hh0 = cvt_bf16x2(v01.y, v01.x);
    uint32_t hh1 = cvt_bf16x2(v23.y, v23.x);
    float l0 = v01.x - __uint_as_float(hh0 << 16);
    float l1 = v01.y - __uint_as_float(hh0 & 0xffff0000u);
    float l2 = v23.x - __uint_as_float(hh1 << 16);
    float l3 = v23.y - __uint_as_float(hh1 & 0xffff0000u);
    uint32_t ll0 = cvt_bf16x2(l1, l0);
    uint32_t ll1 = cvt_bf16x2(l3, l2);
    *(uint2*)(xh + idx) = make_uint2(hh0, hh1);
    *(uint2*)(xl + idx) = make_uint2(ll0, ll1);
}

// ---------------- weight prep helpers ----------------
__device__ __forceinline__ void prep_def(const float* __restrict__ wc,
                                         __nv_bfloat16* h, __nv_bfloat16* l,
                                         int O, int C, int i) {
    int k = i / O, o = i - k * O;
    int n = k / C, c = k - n * C;
    float val = wc[(o * C + c) * 9 + n];
    __nv_bfloat16 hi = __float2bfloat16(val);
    h[i] = hi;
    l[i] = __float2bfloat16(val - __bfloat162float(hi));
}
__device__ __forceinline__ void prep_off(const float* __restrict__ wp,
                                         __nv_bfloat16* h, __nv_bfloat16* l,
                                         int C, int i) {
    int k = i / 40, ch = i - k * 40;
    float val = 0.f;
    if (ch < 18) {
        int n = k / C, c = k - n * C;
        val = wp[(ch * C + c) * 9 + n];
    }
    __nv_bfloat16 hi = __float2bfloat16(val);
    h[i] = hi;
    l[i] = __float2bfloat16(val - __bfloat162float(hi));
}

// ---------------- head kernel: conv1 (f32x2) + all weight preps, one launch ----
__global__ __launch_bounds__(256) void head_kernel(
    const float* __restrict__ x, const float* __restrict__ w1, const float* __restrict__ b1,
    const float* __restrict__ g, const float* __restrict__ be,
    const float* __restrict__ m, const float* __restrict__ v,
    float* __restrict__ out_nhwc,
    const float* wc2, const float* wc3, const float* wc4,
    const float* wp2, const float* wp3, const float* wp4,
    __nv_bfloat16* wth2, __nv_bfloat16* wtl2,
    __nv_bfloat16* wth3, __nv_bfloat16* wtl3,
    __nv_bfloat16* wth4, __nv_bfloat16* wtl4,
    __nv_bfloat16* wph2, __nv_bfloat16* wpl2,
    __nv_bfloat16* wph3, __nv_bfloat16* wpl3,
    __nv_bfloat16* wph4, __nv_bfloat16* wpl4)
{
    int tid = threadIdx.x;
    if (blockIdx.x >= NB*1024/256) {
        int id = (blockIdx.x - NB*1024/256) * 256 + tid;
        const int S1 = 18432, S2 = S1 + 73728, S3 = S2 + 147456;
        const int S4 = S3 + 11520, S5 = S4 + 23040, S6 = S5 + 46080;
        if      (id < S1) prep_def(wc2, wth2, wtl2, 64, 32, id);
        else if (id < S2) prep_def(wc3, wth3, wtl3, 128, 64, id - S1);
        else if (id < S3) prep_def(wc4, wth4, wtl4, 128, 128, id - S2);
        else if (id < S4) prep_off(wp2, wph2, wpl2, 32,  id - S3);
        else if (id < S5) prep_off(wp3, wph3, wpl3, 64,  id - S4);
        else if (id < S6) prep_off(wp4, wph4, wpl4, 128, id - S5);
        return;
    }

    __shared__ float s_w2[27*32];    // transposed: [k][oc]
    __shared__ float s_sc[32], s_sh[32];
    __shared__ float s_o[256*33];

    for (int idx = tid; idx < 32*27; idx += 256) {
        int oc = idx / 27, k = idx - oc*27;
        s_w2[k*32 + oc] = w1[idx];
    }
    if (tid < 32) {
        float sc = g[tid] / sqrtf(v[tid] + 1e-5f);
        s_sc[tid] = sc;
        s_sh[tid] = be[tid] - m[tid]*sc + b1[tid]*sc;
    }
    __syncthreads();

    int q = blockIdx.x * 256 + tid;
    int b = q >> 10;
    int p = q & 1023;
    int i = p >> 5, j = p & 31;

    float in[27];
    const float* xb = x + (size_t)b * 3 * 1024;
    #pragma unroll
    for (int c = 0; c < 3; c++)
        #pragma unroll
        for (int ky = 0; ky < 3; ky++)
            #pragma unroll
            for (int kx = 0; kx < 3; kx++) {
                int yy = i - 1 + ky, xx = j - 1 + kx;
                float val = 0.f;
                if ((unsigned)yy < 32u && (unsigned)xx < 32u)
                    val = xb[c*1024 + yy*32 + xx];
                in[c*9 + ky*3 + kx] = val;
            }

    unsigned long long acc2[16];
    #pragma unroll
    for (int pp = 0; pp < 16; pp++) acc2[pp] = 0ull;
    #pragma unroll
    for (int k = 0; k < 27; k++) {
        unsigned long long ind = pk2(in[k], in[k]);
        const ulonglong2* wr = (const ulonglong2*)(s_w2 + k*32);
        #pragma unroll
        for (int pq = 0; pq < 8; pq++) {
            ulonglong2 wv = wr[pq];
            fma2(acc2[pq*2    ], ind, wv.x);
            fma2(acc2[pq*2 + 1], ind, wv.y);
        }
    }
    #pragma unroll
    for (int pp = 0; pp < 16; pp++) {
        float2 a = upk2(acc2[pp]);
        int oc = pp*2;
        s_o[tid*33 + oc    ] = fmaxf(a.x * s_sc[oc]   + s_sh[oc],   0.f);
        s_o[tid*33 + oc + 1] = fmaxf(a.y * s_sc[oc+1] + s_sh[oc+1], 0.f);
    }
    __syncthreads();

    size_t base = (size_t)blockIdx.x * 256 * 32;
    for (int idx = tid; idx < 256*32; idx += 256) {
        int pp = idx >> 5, oc = idx & 31;
        out_nhwc[base + idx] = s_o[pp*33 + oc];
    }
}

// ---------------- offconv_tc: 3x3 conv C->18 as bf16x3 tensor GEMM ----------------
// feat (B,H,W,C) NHWC -> off (B,hw,18) position-major. TILE_M=128*FM, 8 warps.
// Distance-2 gather pipeline; B weights via cp.async (distance-1).
template<int C, int S, int H, int W, int FM, int MB>
__global__ __launch_bounds__(256, MB) void offconv_tc(
    const float* __restrict__ feat_nhwc,
    const __nv_bfloat16* __restrict__ wph,
    const __nv_bfloat16* __restrict__ wpl,
    const float* __restrict__ bp,
    float* __restrict__ off)
{
    constexpr int K  = C * 9;
    constexpr int KC = 32;
    constexpr int NCH = K / KC;
    constexpr int TILE_M = 128 * FM;
    constexpr int ITEMS = TILE_M * 8 / 256;   // gather items per thread (4*FM)
    constexpr int KP = 40;          // padded A row (bf16)
    constexpr int NPB = 40;         // padded B row (bf16), 24 used
    constexpr int h  = (H - 1) / S + 1;
    constexpr int w  = (W - 1) / S + 1;
    constexpr int HW = h * w;

    extern __shared__ char smem[];
    int* s_ni = (int*)smem;                                   // TILE_M*9
    uint32_t* s_xa = (uint32_t*)(s_ni + TILE_M*9);            // [2][2][TILE_M*20]
    __nv_bfloat16* s_wb = (__nv_bfloat16*)(s_xa + 4*TILE_M*20); // [2][2][KC*NPB]
    float* s_bp = (float*)(s_wb + 4*KC*NPB);                  // 20

    int tid = threadIdx.x;
    int gbase = blockIdx.x * TILE_M;
    int warp = tid >> 5, lane = tid & 31;
    int tmw = warp * 16 * FM;
    int lm = lane & 15, lh = lane >> 4;

    if (tid < 18) s_bp[tid] = bp[tid];

    // neighbor indices for all 9 taps
    for (int e = tid; e < TILE_M*9; e += 256) {
        int t = e / 9, n = e - t*9;
        int gpos = gbase + t;
        int b = gpos / HW, p = gpos - b*HW;
        int i = p / w, j = p - i*w;
        int yy = i*S - 1 + n/3, xx = j*S - 1 + (n - (n/3)*3);
        s_ni[e] = ((unsigned)yy < (unsigned)H && (unsigned)xx < (unsigned)W)
                  ? b*H*W*C + (yy*W + xx)*C : -1;
    }
    __syncthreads();

    auto oload = [&](int n, int c0, int idx, float4& v) {
        int t = idx >> 3, cc4 = idx & 7;
        int ix = s_ni[t*9 + n];
        v = make_float4(0.f, 0.f, 0.f, 0.f);
        if (ix >= 0) v = *(const float4*)(feat_nhwc + ix + c0 + cc4*4);
    };
    auto ostore = [&](int buf, int idx, const float4& v) {
        int t = idx >> 3, cc4 = idx & 7;
        uint32_t* xh = s_xa + buf*(2*TILE_M*20);
        uint32_t* xl = xh + TILE_M*20;
        split4_store(xh, xl, t*20 + cc4*2,
                     make_float2(v.x, v.y), make_float2(v.z, v.w));
    };
    // B copy: cp.async GMEM -> SMEM, no register holding (5 int4 per row)
    auto bcopy = [&](int k0, int buf) {
        if (tid < KC*5) {
            int row = tid / 5, gq = tid - row*5;
            __nv_bfloat16* wh = s_wb + buf*(2*KC*NPB);
            __nv_bfloat16* wl = wh + KC*NPB;
            cpa16(sptr(wh + row*NPB + gq*8), wph + (size_t)(k0+row)*40 + gq*8);
            cpa16(sptr(wl + row*NPB + gq*8), wpl + (size_t)(k0+row)*40 + gq*8);
        }
        cpa_commit();
    };

    float acc[FM][3][4];
    #pragma unroll
    for (int f = 0; f < FM; f++)
        #pragma unroll
        for (int q = 0; q < 3; q++)
            #pragma unroll
            for (int r = 0; r < 4; r++) acc[f][q][r] = 0.f;

    uint32_t aab = ((tmw + lm)*KP + lh*8) * 2;
    uint32_t bab = (lm*NPB + lh*8) * 2;

    auto mma_step = [&](int cur, int step) {
        uint32_t xh_s = sptr(s_xa + cur*(2*TILE_M*20));
        uint32_t xl_s = xh_s + TILE_M*20*4;
        uint32_t wh_s = sptr(s_wb + cur*(2*KC*NPB));
        uint32_t wl_s = wh_s + KC*NPB*2;
        uint32_t koffA = (uint32_t)(step*16*2);
        uint32_t koffB = (uint32_t)(step*16*NPB*2);
        uint32_t ah[FM][4], al[FM][4];
        #pragma unroll
        for (int f = 0; f < FM; f++) {
            uint32_t aoff = aab + (uint32_t)(f*16*KP*2) + koffA;
            ldsm4(ah[f][0], ah[f][1], ah[f][2], ah[f][3], xh_s + aoff);
            ldsm4(al[f][0], al[f][1], al[f][2], al[f][3], xl_s + aoff);
        }
        #pragma unroll
        for (int q16 = 0; q16 < 2; q16++) {
            uint32_t boff = bab + koffB + (uint32_t)(q16*16*2);
            uint32_t bh[4], bl[4];
            ldsm4t(bh[0], bh[1], bh[2], bh[3], wh_s + boff);
            ldsm4t(bl[0], bl[1], bl[2], bl[3], wl_s + boff);
            int jmax = (q16 == 0) ? 2 : 1;   // cols 24+ are zero pad
            for (int j = 0; j < jmax; j++) {
                #pragma unroll
                for (int f = 0; f < FM; f++) {
                    float* d = acc[f][q16*2 + j];
                    mma16816(d, ah[f], bh[j*2], bh[j*2+1]);
                    mma16816(d, ah[f], bl[j*2], bl[j*2+1]);
                    mma16816(d, al[f], bh[j*2], bh[j*2+1]);
                }
            }
        }
    };

    float4 hv[ITEMS];   // held chunk-(i+1) gather data
    // prologue: fill buffer 0; preload chunk 1 gathers into held regs
    {
        float4 v;
        #pragma unroll
        for (int u = 0; u < ITEMS; u++) {
            oload(0, 0, tid + u*256, v);
            ostore(0, tid + u*256, v);
        }
        bcopy(0, 0);
        if (NCH > 1) {
            int n1 = KC / C, c01 = KC - n1*C;
            #pragma unroll
            for (int u = 0; u < ITEMS; u++) oload(n1, c01, tid + u*256, hv[u]);
        }
        cpa_wait0();
    }
    __syncthreads();

    for (int i = 0; i < NCH; i++) {
        int cur = i & 1, nxt = cur ^ 1;
        if (i + 1 < NCH) {   // store chunk i+1 gathers; launch B copy for i+1
            #pragma unroll
            for (int u = 0; u < ITEMS; u++) ostore(nxt, tid + u*256, hv[u]);
            bcopy((i+1)*KC, nxt);
        }
        if (i + 2 < NCH) {   // issue gather loads for chunk i+2
            int k2 = (i+2)*KC;
            int n2 = k2 / C, c02 = k2 - n2*C;
            #pragma unroll
            for (int u = 0; u < ITEMS; u++) oload(n2, c02, tid + u*256, hv[u]);
        }
        mma_step(cur, 0);
        mma_step(cur, 1);
        cpa_wait0();
        __syncthreads();
    }

    // epilogue: add bias, store (pos, 18)
    int lq = lane >> 2, lr = lane & 3;
    #pragma unroll
    for (int f = 0; f < FM; f++) {
        #pragma unroll
        for (int q = 0; q < 3; q++) {
            int col = q*8 + lr*2;
            if (col < 18) {
                float b0 = s_bp[col], b1 = s_bp[col+1];
                int row0 = gbase + tmw + f*16 + lq;
                int row1 = row0 + 8;
                float2 r0 = make_float2(acc[f][q][0] + b0, acc[f][q][1] + b1);
                float2 r1 = make_float2(acc[f][q][2] + b0, acc[f][q][3] + b1);
                *(float2*)(off + (size_t)row0*18 + col) = r0;
                *(float2*)(off + (size_t)row1*18 + col) = r1;
            }
        }
    }
}

// ---------------- deform: distance-2 gather pipeline + cp.async B + bf16x3 mma ----
template<int C, int O, int S, int H, int W, int TILE_M, int WM, int WN, int MB>
__global__ __launch_bounds__(256, MB) void deform_v11(
    const float* __restrict__ feat_nhwc,
    const float* __restrict__ off,
    const __nv_bfloat16* __restrict__ wth,
    const __nv_bfloat16* __restrict__ wtl,
    const float* __restrict__ g, const float* __restrict__ be,
    const float* __restrict__ m, const float* __restrict__ v,
    float* __restrict__ out_nhwc)
{
    constexpr int K    = C * 9;
    constexpr int KC   = 32;
    constexpr int NCH  = K / KC;
    constexpr int KP   = 40;            // padded A row (bf16)
    constexpr int NP   = O + 8;         // padded B row (bf16)
    constexpr int NWC  = O / WN;        // cols per warp
    constexpr int QMAX = NWC / 16;
    constexpr int QN   = NWC / 8;
    constexpr int GPR  = O / 8;
    constexpr int BIT  = (KC*GPR) / 256;   // 1 (O=64) or 2 (O=128)
    constexpr int h    = (H - 1) / S + 1;
    constexpr int w    = (W - 1) / S + 1;
    constexpr int HW   = h * w;
    static_assert(WM * WN == 8 && TILE_M == WM * 16, "warp map");
    static_assert(TILE_M * 8 == 512, "2 gather items per thread");

    extern __shared__ char smem[];
    float* s_mg = (float*)smem;                               // TILE_M*9*4
    int*   s_mi = (int*)(s_mg + TILE_M*9*4);                  // TILE_M*9*4
    uint32_t* s_xa = (uint32_t*)(s_mi + TILE_M*9*4);          // [2][2][TILE_M*20]
    __nv_bfloat16* s_wb = (__nv_bfloat16*)(s_xa + 4*TILE_M*20); // [2][2][KC*NP]
    float* s_sc = (float*)(s_wb + 4*KC*NP);                   // O
    float* s_sh = s_sc + O;                                   // O

    int tid = threadIdx.x;
    int gbase = blockIdx.x * TILE_M;
    int warp = tid >> 5, lane = tid & 31;
    int warpM = warp % WM, warpN = warp / WM;
    int tmw = warpM * 16;
    int to0 = warpN * NWC;
    int lm = lane & 15, lh = lane >> 4;

    if (tid < O) {
        float s = g[tid] / sqrtf(v[tid] + 1e-5f);
        s_sc[tid] = s;
        s_sh[tid] = be[tid] - m[tid]*s;
    }

    // ---- bilinear metadata for ALL 9 taps, once ----
    for (int e = tid; e < TILE_M*9; e += 256) {
        int t = e / 9, n = e - t*9;
        int gpos = gbase + t;
        int b = gpos / HW, p = gpos - b*HW;
        int i = p / w, j = p - i*w;
        float offx = off[(size_t)gpos*18 + n];
        float offy = off[(size_t)gpos*18 + 9 + n];
        float px = (float)(i*S + (n/3)) + offx;
        float py = (float)(j*S + (n - (n/3)*3)) + offy;
        const float HB = (float)(H + 1), WB = (float)(W + 1);
        float qx0 = floorf(px);
        float fx0 = fminf(fmaxf(qx0,       0.f), HB);
        float fx1 = fminf(fmaxf(qx0 + 1.f, 0.f), HB);
        float pxc = fminf(fmaxf(px,        0.f), HB);
        float qy0 = floorf(py);
        float fy0 = fminf(fmaxf(qy0,       0.f), WB);
        float fy1 = fminf(fmaxf(qy0 + 1.f, 0.f), WB);
        float pyc = fminf(fmaxf(py,        0.f), WB);
        float glt = (1.f + (fx0 - pxc)) * (1.f + (fy0 - pyc));
        float grb = (1.f - (fx1 - pxc)) * (1.f - (fy1 - pyc));
        float glb = (1.f + (fx0 - pxc)) * (1.f - (fy1 - pyc));
        float grt = (1.f - (fx1 - pxc)) * (1.f + (fy0 - pyc));
        int x0 = (int)fx0, x1 = (int)fx1, y0 = (int)fy0, y1 = (int)fy1;
        bool bx0 = (x0 >= 1 && x0 <= H), bx1 = (x1 >= 1 && x1 <= H);
        bool by0 = (y0 >= 1 && y0 <= W), by1 = (y1 >= 1 && y1 <= W);
        int base = b * H * W * C;
        s_mg[e*4+0] = (bx0 && by0) ? glt : 0.f;
        s_mg[e*4+1] = (bx1 && by1) ? grb : 0.f;
        s_mg[e*4+2] = (bx0 && by1) ? glb : 0.f;
        s_mg[e*4+3] = (bx1 && by0) ? grt : 0.f;
        s_mi[e*4+0] = (bx0 && by0) ? base + ((x0-1)*W + (y0-1))*C : 0;
        s_mi[e*4+1] = (bx1 && by1) ? base + ((x1-1)*W + (y1-1))*C : 0;
        s_mi[e*4+2] = (bx0 && by1) ? base + ((x0-1)*W + (y1-1))*C : 0;
        s_mi[e*4+3] = (bx1 && by0) ? base + ((x1-1)*W + (y0-1))*C : 0;
    }
    __syncthreads();

    // gather item = (position t, 4-channel group cc4); 8 lanes share a corner line.
    struct GD { ulonglong2 a0, a1, a2, a3; };
    auto gload = [&](int n, int c0, int idx, GD& d) {
        int t = idx >> 3, cc4 = idx & 7;
        int c = c0 + cc4*4;
        const int4 i4 = *(const int4*)(s_mi + (t*9+n)*4);
        d.a0 = *(const ulonglong2*)(feat_nhwc + i4.x + c);
        d.a1 = *(const ulonglong2*)(feat_nhwc + i4.y + c);
        d.a2 = *(const ulonglong2*)(feat_nhwc + i4.z + c);
        d.a3 = *(const ulonglong2*)(feat_nhwc + i4.w + c);
    };
    auto gstore = [&](int n, int buf, int idx, const GD& d) {
        int t = idx >> 3, cc4 = idx & 7;
        uint32_t* xh = s_xa + buf*(2*TILE_M*20);
        uint32_t* xl = xh + TILE_M*20;
        const float4 g4 = *(const float4*)(s_mg + (t*9+n)*4);
        unsigned long long gx = pk2(g4.x, g4.x), gy = pk2(g4.y, g4.y);
        unsigned long long gz = pk2(g4.z, g4.z), gw = pk2(g4.w, g4.w);
        unsigned long long s01 = 0ull, s23 = 0ull;
        fma2(s01, gx, d.a0.x); fma2(s23, gx, d.a0.y);
        fma2(s01, gy, d.a1.x); fma2(s23, gy, d.a1.y);
        fma2(s01, gz, d.a2.x); fma2(s23, gz, d.a2.y);
        fma2(s01, gw, d.a3.x); fma2(s23, gw, d.a3.y);
        split4_store(xh, xl, t*20 + cc4*2, upk2(s01), upk2(s23));
    };
    // B copy: cp.async directly GMEM -> SMEM (no register holding)
    auto bcopy = [&](int k0, int buf) {
        __nv_bfloat16* wh = s_wb + buf*(2*KC*NP);
        __nv_bfloat16* wl = wh + KC*NP;
        #pragma unroll
        for (int ii = 0; ii < BIT; ii++) {
            int idx = tid + ii*256;
            int row = idx / GPR, gq = idx - row*GPR;
            cpa16(sptr(wh + row*NP + gq*8), wth + (size_t)(k0+row)*O + gq*8);
            cpa16(sptr(wl + row*NP + gq*8), wtl + (size_t)(k0+row)*O + gq*8);
        }
        cpa_commit();
    };

    float acc[QN][4];
    #pragma unroll
    for (int q = 0; q < QN; q++)
        #pragma unroll
        for (int r = 0; r < 4; r++) acc[q][r] = 0.f;

    uint32_t aab = ((tmw + lm)*KP + lh*8) * 2;
    uint32_t bab = (lm*NP + to0 + lh*8) * 2;

    auto mma_step = [&](int cur, int step) {
        uint32_t xh_s = sptr(s_xa + cur*(2*TILE_M*20));
        uint32_t xl_s = xh_s + TILE_M*20*4;
        uint32_t wh_s = sptr(s_wb + cur*(2*KC*NP));
        uint32_t wl_s = wh_s + KC*NP*2;
        uint32_t koffA = (uint32_t)(step*16*2);
        uint32_t koffB = (uint32_t)(step*16*NP*2);
        uint32_t ah[4], al[4];
        ldsm4(ah[0], ah[1], ah[2], ah[3], xh_s + aab + koffA);
        ldsm4(al[0], al[1], al[2], al[3], xl_s + aab + koffA);
        #pragma unroll
        for (int q16 = 0; q16 < QMAX; q16++) {
            uint32_t boff = bab + koffB + (uint32_t)(q16*16*2);
            uint32_t bh[4], bl[4];
            ldsm4t(bh[0], bh[1], bh[2], bh[3], wh_s + boff);
            ldsm4t(bl[0], bl[1], bl[2], bl[3], wl_s + boff);
            #pragma unroll
            for (int j = 0; j < 2; j++) {
                float* d = acc[q16*2 + j];
                mma16816(d, ah, bh[j*2], bh[j*2+1]);
                mma16816(d, ah, bl[j*2], bl[j*2+1]);
                mma16816(d, al, bh[j*2], bh[j*2+1]);
            }
        }
    };

    GD hA0, hA1;   // held chunk-(i+1) corner data
    // prologue: fill buffer 0; preload chunk 1 gathers into held regs
    {
        GD d;
        gload(0, 0, tid, d);       gstore(0, 0, tid, d);
        gload(0, 0, tid+256, d);   gstore(0, 0, tid+256, d);
        bcopy(0, 0);
        if (NCH > 1) {
            int n1 = KC / C, c01 = KC - n1*C;
            gload(n1, c01, tid, hA0);
            gload(n1, c01, tid+256, hA1);
        }
        cpa_wait0();
    }
    __syncthreads();

    for (int i = 0; i < NCH; i++) {
        int cur = i & 1, nxt = cur ^ 1;
        if (i + 1 < NCH) {   // store chunk i+1 gathers; launch B copy for i+1
            int k1 = (i+1)*KC;
            int n1 = k1 / C;
            gstore(n1, nxt, tid, hA0);
            gstore(n1, nxt, tid+256, hA1);
            bcopy(k1, nxt);
        }
        if (i + 2 < NCH) {   // issue gather loads for chunk i+2
            int k2 = (i+2)*KC;
            int n2 = k2 / C, c02 = k2 - n2*C;
            gload(n2, c02, tid, hA0);
            gload(n2, c02, tid+256, hA1);
        }
        mma_step(cur, 0);
        mma_step(cur, 1);
        cpa_wait0();
        __syncthreads();
    }

    // epilogue: BN + ReLU from register fragments
    int lq = lane >> 2, lr = lane & 3;
    #pragma unroll
    for (int q = 0; q < QN; q++) {
        int col = to0 + q*8 + lr*2;
        float sc0 = s_sc[col], sc1 = s_sc[col+1];
        float sh0 = s_sh[col], sh1 = s_sh[col+1];
        int row0 = gbase + tmw + lq;
        int row1 = row0 + 8;
        float2 r0, r1;
        r0.x = fmaxf(acc[q][0]*sc0 + sh0, 0.f);
        r0.y = fmaxf(acc[q][1]*sc1 + sh1, 0.f);
        r1.x = fmaxf(acc[q][2]*sc0 + sh0, 0.f);
        r1.y = fmaxf(acc[q][3]*sc1 + sh1, 0.f);
        *(float2*)(out_nhwc + (size_t)row0*O + col) = r0;
        *(float2*)(out_nhwc + (size_t)row1*O + col) = r1;
    }
}

// ---------------- global avg pool (8x8, NHWC) + FC (128 -> 100) ----------------
__global__ __launch_bounds__(128) void poolfc_kernel(
    const float* __restrict__ h4n,
    const float* __restrict__ wcls, const float* __restrict__ bcls,
    float* __restrict__ out)
{
    __shared__ float s_p[128];
    int b = blockIdx.x, tid = threadIdx.x;
    const float* hb = h4n + (size_t)b * 64 * 128 + tid;
    float s = 0.f;
    #pragma unroll
    for (int k = 0; k < 64; k++) s += hb[k*128];
    s_p[tid] = s * (1.f / 64.f);
    __syncthreads();
    if (tid < 100) {
        float a = bcls[tid];
        const float* wr = wcls + tid*128;
        #pragma unroll 16
        for (int o = 0; o < 128; o++) a += s_p[o] * wr[o];
        out[b*100 + tid] = a;
    }
}

// ---------------- launch ----------------
extern "C" void kernel_launch(void* const* d_in, const int* in_sizes, int n_in,
                              void* d_out, int out_size)
{
    (void)in_sizes; (void)n_in; (void)out_size;
    const float* x    = (const float*)d_in[0];
    const float* w1   = (const float*)d_in[1];
    const float* b1   = (const float*)d_in[2];
    const float* g1   = (const float*)d_in[3];
    const float* be1  = (const float*)d_in[4];
    const float* m1   = (const float*)d_in[5];
    const float* v1   = (const float*)d_in[6];
    const float* wp2  = (const float*)d_in[7];
    const float* bp2  = (const float*)d_in[8];
    const float* wc2  = (const float*)d_in[9];
    const float* g2   = (const float*)d_in[10];
    const float* be2  = (const float*)d_in[11];
    const float* m2   = (const float*)d_in[12];
    const float* v2   = (const float*)d_in[13];
    const float* wp3  = (const float*)d_in[14];
    const float* bp3  = (const float*)d_in[15];
    const float* wc3  = (const float*)d_in[16];
    const float* g3   = (const float*)d_in[17];
    const float* be3  = (const float*)d_in[18];
    const float* m3   = (const float*)d_in[19];
    const float* v3   = (const float*)d_in[20];
    const float* wp4  = (const float*)d_in[21];
    const float* bp4  = (const float*)d_in[22];
    const float* wc4  = (const float*)d_in[23];
    const float* g4   = (const float*)d_in[24];
    const float* be4  = (const float*)d_in[25];
    const float* m4   = (const float*)d_in[26];
    const float* v4   = (const float*)d_in[27];
    const float* wcls = (const float*)d_in[28];
    const float* bcls = (const float*)d_in[29];
    float* out = (float*)d_out;

    float *h1n, *off2, *h2n, *off3, *h3n, *off4, *h4n;
    __nv_bfloat16 *wth2, *wtl2, *wth3, *wtl3, *wth4, *wtl4;
    __nv_bfloat16 *wph2, *wpl2, *wph3, *wpl3, *wph4, *wpl4;
    cudaGetSymbolAddress((void**)&h1n, g_h1n);
    cudaGetSymbolAddress((void**)&off2,g_off2);
    cudaGetSymbolAddress((void**)&h2n, g_h2n);
    cudaGetSymbolAddress((void**)&off3,g_off3);
    cudaGetSymbolAddress((void**)&h3n, g_h3n);
    cudaGetSymbolAddress((void**)&off4,g_off4);
    cudaGetSymbolAddress((void**)&h4n, g_h4n);
    cudaGetSymbolAddress((void**)&wth2, g_wth2);
    cudaGetSymbolAddress((void**)&wtl2, g_wtl2);
    cudaGetSymbolAddress((void**)&wth3, g_wth3);
    cudaGetSymbolAddress((void**)&wtl3, g_wtl3);
    cudaGetSymbolAddress((void**)&wth4, g_wth4);
    cudaGetSymbolAddress((void**)&wtl4, g_wtl4);
    cudaGetSymbolAddress((void**)&wph2, g_wph2);
    cudaGetSymbolAddress((void**)&wpl2, g_wpl2);
    cudaGetSymbolAddress((void**)&wph3, g_wph3);
    cudaGetSymbolAddress((void**)&wpl3, g_wpl3);
    cudaGetSymbolAddress((void**)&wph4, g_wph4);
    cudaGetSymbolAddress((void**)&wpl4, g_wpl4);

    // head: conv1 + all weight preps in one launch
    head_kernel<<<NB*1024/256 + 1251, 256>>>(
        x, w1, b1, g1, be1, m1, v1, h1n,
        wc2, wc3, wc4, wp2, wp3, wp4,
        wth2, wtl2, wth3, wtl3, wth4, wtl4,
        wph2, wpl2, wph3, wpl3, wph4, wpl4);

    // shared-mem sizes
    auto off_dsm = [](int TM) {
        return (size_t)TM*9*4 + (size_t)4*TM*20*4 + (size_t)4*32*40*2 + 80;
    };
    auto def_dsm = [](int TM, int O) {
        return (size_t)TM*9*4*8 + (size_t)4*TM*20*4 + (size_t)4*32*(O+8)*2
             + (size_t)O*8;
    };

    // L2: 32 -> 64, stride 2 (32x32 -> 16x16)
    {
        size_t osm = off_dsm(256);
        cudaFuncSetAttribute(offconv_tc<32,2,32,32,2,2>,
                             cudaFuncAttributeMaxDynamicSharedMemorySize, (int)osm);
        offconv_tc<32,2,32,32,2,2><<<NB*256/256, 256, osm>>>(h1n, wph2, wpl2, bp2, off2);
        size_t dsm = def_dsm(64, 64);
        cudaFuncSetAttribute(deform_v11<32,64,2,32,32,64,4,2,2>,
                             cudaFuncAttributeMaxDynamicSharedMemorySize, (int)dsm);
        deform_v11<32,64,2,32,32,64,4,2,2><<<NB*256/64, 256, dsm>>>(
            h1n, off2, wth2, wtl2, g2, be2, m2, v2, h2n);
    }
    // L3: 64 -> 128, stride 1 (16x16)
    {
        size_t osm = off_dsm(256);
        cudaFuncSetAttribute(offconv_tc<64,1,16,16,2,2>,
                             cudaFuncAttributeMaxDynamicSharedMemorySize, (int)osm);
        offconv_tc<64,1,16,16,2,2><<<NB*256/256, 256, osm>>>(h2n, wph3, wpl3, bp3, off3);
        size_t dsm = def_dsm(64, 128);
        cudaFuncSetAttribute(deform_v11<64,128,1,16,16,64,4,2,2>,
                             cudaFuncAttributeMaxDynamicSharedMemorySize, (int)dsm);
        deform_v11<64,128,1,16,16,64,4,2,2><<<NB*256/64, 256, dsm>>>(
            h2n, off3, wth3, wtl3, g3, be3, m3, v3, h3n);
    }
    // L4: 128 -> 128, stride 2 (16x16 -> 8x8)
    {
        size_t osm = off_dsm(128);
        cudaFuncSetAttribute(offconv_tc<128,2,16,16,1,3>,
                             cudaFuncAttributeMaxDynamicSharedMemorySize, (int)osm);
        offconv_tc<128,2,16,16,1,3><<<NB*64/128, 256, osm>>>(h3n, wph4, wpl4, bp4, off4);
        size_t dsm = def_dsm(64, 128);
        cudaFuncSetAttribute(deform_v11<128,128,2,16,16,64,4,2,2>,
                             cudaFuncAttributeMaxDynamicSharedMemorySize, (int)dsm);
        deform_v11<128,128,2,16,16,64,4,2,2><<<NB*64/64, 256, dsm>>>(
            h3n, off4, wth4, wtl4, g4, be4, m4, v4, h4n);
    }
    // pool + FC
    poolfc_kernel<<<NB, 128>>>(h4n, wcls, bcls, out);
}

// round 14
// speedup vs baseline: 1.0444x; 1.0444x over previous
#include <cuda_runtime.h>
#include <cuda_bf16.h>
#include <cstdint>

#define NB 256   // batch

// ---------------- scratch (device globals; no allocation) ----------------
__device__ float g_h1n [(size_t)NB*32*32*32];   // NHWC
__device__ float g_off2[(size_t)NB*16*16*18];   // position-major (b,hw,18)
__device__ float g_h2n [(size_t)NB*64*16*16];
__device__ float g_off3[(size_t)NB*16*16*18];
__device__ float g_h3n [(size_t)NB*128*16*16];
__device__ float g_off4[(size_t)NB*8*8*18];
__device__ float g_h4n [(size_t)NB*128*8*8];
__device__ __nv_bfloat16 g_wth2[64*288],  g_wtl2[64*288];    // deform weights [k][O]
__device__ __nv_bfloat16 g_wth3[128*576], g_wtl3[128*576];
__device__ __nv_bfloat16 g_wth4[128*1152],g_wtl4[128*1152];
__device__ __nv_bfloat16 g_wph2[288*40],  g_wpl2[288*40];    // offset weights [k][40]
__device__ __nv_bfloat16 g_wph3[576*40],  g_wpl3[576*40];
__device__ __nv_bfloat16 g_wph4[1152*40], g_wpl4[1152*40];

// ---------------- small asm helpers ----------------
__device__ __forceinline__ unsigned long long pk2(float lo, float hi) {
    unsigned long long r;
    asm("mov.b64 %0, {%1, %2};" : "=l"(r) : "f"(lo), "f"(hi));
    return r;
}
__device__ __forceinline__ void fma2(unsigned long long& d,
                                     unsigned long long a, unsigned long long b) {
    asm("fma.rn.f32x2 %0, %1, %2, %0;" : "+l"(d) : "l"(a), "l"(b));
}
__device__ __forceinline__ float2 upk2(unsigned long long v) {
    float2 r;
    asm("mov.b64 {%0, %1}, %2;" : "=f"(r.x), "=f"(r.y) : "l"(v));
    return r;
}
__device__ __forceinline__ uint32_t cvt_bf16x2(float hi, float lo) {
    uint32_t r;
    asm("cvt.rn.bf16x2.f32 %0, %1, %2;" : "=r"(r) : "f"(hi), "f"(lo));
    return r;
}
__device__ __forceinline__ uint32_t sptr(const void* p) {
    return (uint32_t)__cvta_generic_to_shared(p);
}
__device__ __forceinline__ void cpa16(uint32_t dst, const void* src) {
    asm volatile("cp.async.cg.shared.global [%0], [%1], 16;"
                 :: "r"(dst), "l"(src) : "memory");
}
__device__ __forceinline__ void cpa_commit() {
    asm volatile("cp.async.commit_group;" ::: "memory");
}
__device__ __forceinline__ void cpa_wait0() {
    asm volatile("cp.async.wait_group 0;" ::: "memory");
}
__device__ __forceinline__ void ldsm4(uint32_t& r0, uint32_t& r1, uint32_t& r2,
                                      uint32_t& r3, uint32_t addr) {
    asm volatile("ldmatrix.sync.aligned.m8n8.x4.shared.b16 {%0,%1,%2,%3},[%4];"
                 : "=r"(r0), "=r"(r1), "=r"(r2), "=r"(r3) : "r"(addr));
}
__device__ __forceinline__ void ldsm4t(uint32_t& r0, uint32_t& r1, uint32_t& r2,
                                       uint32_t& r3, uint32_t addr) {
    asm volatile("ldmatrix.sync.aligned.m8n8.x4.trans.shared.b16 {%0,%1,%2,%3},[%4];"
                 : "=r"(r0), "=r"(r1), "=r"(r2), "=r"(r3) : "r"(addr));
}
__device__ __forceinline__ void mma16816(float* d, const uint32_t* a,
                                         uint32_t b0, uint32_t b1) {
    asm volatile(
        "mma.sync.aligned.m16n8k16.row.col.f32.bf16.bf16.f32 "
        "{%0,%1,%2,%3},{%4,%5,%6,%7},{%8,%9},{%0,%1,%2,%3};"
        : "+f"(d[0]), "+f"(d[1]), "+f"(d[2]), "+f"(d[3])
        : "r"(a[0]), "r"(a[1]), "r"(a[2]), "r"(a[3]), "r"(b0), "r"(b1));
}
// split 4 f32 into bf16 hi/lo planes and store (2x uint2)
__device__ __forceinline__ void split4_store(uint32_t* xh, uint32_t* xl, int idx,
                                             float2 v01, float2 v23) {
    uint32_t hh0 = cvt_bf16x2(v01.y, v01.x);
    uint32_t hh1 = cvt_bf16x2(v23.y, v23.x);
    float l0 = v01.x - __uint_as_float(hh0 << 16);
    float l1 = v01.y - __uint_as_float(hh0 & 0xffff0000u);
    float l2 = v23.x - __uint_as_float(hh1 << 16);
    float l3 = v23.y - __uint_as_float(hh1 & 0xffff0000u);
    uint32_t ll0 = cvt_bf16x2(l1, l0);
    uint32_t ll1 = cvt_bf16x2(l3, l2);
    *(uint2*)(xh + idx) = make_uint2(hh0, hh1);
    *(uint2*)(xl + idx) = make_uint2(ll0, ll1);
}

// ---------------- weight prep helpers ----------------
__device__ __forceinline__ void prep_def(const float* __restrict__ wc,
                                         __nv_bfloat16* h, __nv_bfloat16* l,
                                         int O, int C, int i) {
    int k = i / O, o = i - k * O;
    int n = k / C, c = k - n * C;
    float val = wc[(o * C + c) * 9 + n];
    __nv_bfloat16 hi = __float2bfloat16(val);
    h[i] = hi;
    l[i] = __float2bfloat16(val - __bfloat162float(hi));
}
__device__ __forceinline__ void prep_off(const float* __restrict__ wp,
                                         __nv_bfloat16* h, __nv_bfloat16* l,
                                         int C, int i) {
    int k = i / 40, ch = i - k * 40;
    float val = 0.f;
    if (ch < 18) {
        int n = k / C, c = k - n * C;
        val = wp[(ch * C + c) * 9 + n];
    }
    __nv_bfloat16 hi = __float2bfloat16(val);
    h[i] = hi;
    l[i] = __float2bfloat16(val - __bfloat162float(hi));
}

// ---------------- head kernel: conv1 (f32x2) + all weight preps, one launch ----
__global__ __launch_bounds__(256) void head_kernel(
    const float* __restrict__ x, const float* __restrict__ w1, const float* __restrict__ b1,
    const float* __restrict__ g, const float* __restrict__ be,
    const float* __restrict__ m, const float* __restrict__ v,
    float* __restrict__ out_nhwc,
    const float* wc2, const float* wc3, const float* wc4,
    const float* wp2, const float* wp3, const float* wp4,
    __nv_bfloat16* wth2, __nv_bfloat16* wtl2,
    __nv_bfloat16* wth3, __nv_bfloat16* wtl3,
    __nv_bfloat16* wth4, __nv_bfloat16* wtl4,
    __nv_bfloat16* wph2, __nv_bfloat16* wpl2,
    __nv_bfloat16* wph3, __nv_bfloat16* wpl3,
    __nv_bfloat16* wph4, __nv_bfloat16* wpl4)
{
    int tid = threadIdx.x;
    if (blockIdx.x >= NB*1024/256) {
        int id = (blockIdx.x - NB*1024/256) * 256 + tid;
        const int S1 = 18432, S2 = S1 + 73728, S3 = S2 + 147456;
        const int S4 = S3 + 11520, S5 = S4 + 23040, S6 = S5 + 46080;
        if      (id < S1) prep_def(wc2, wth2, wtl2, 64, 32, id);
        else if (id < S2) prep_def(wc3, wth3, wtl3, 128, 64, id - S1);
        else if (id < S3) prep_def(wc4, wth4, wtl4, 128, 128, id - S2);
        else if (id < S4) prep_off(wp2, wph2, wpl2, 32,  id - S3);
        else if (id < S5) prep_off(wp3, wph3, wpl3, 64,  id - S4);
        else if (id < S6) prep_off(wp4, wph4, wpl4, 128, id - S5);
        return;
    }

    __shared__ float s_w2[27*32];    // transposed: [k][oc]
    __shared__ float s_sc[32], s_sh[32];
    __shared__ float s_o[256*33];

    for (int idx = tid; idx < 32*27; idx += 256) {
        int oc = idx / 27, k = idx - oc*27;
        s_w2[k*32 + oc] = w1[idx];
    }
    if (tid < 32) {
        float sc = g[tid] / sqrtf(v[tid] + 1e-5f);
        s_sc[tid] = sc;
        s_sh[tid] = be[tid] - m[tid]*sc + b1[tid]*sc;
    }
    __syncthreads();

    int q = blockIdx.x * 256 + tid;
    int b = q >> 10;
    int p = q & 1023;
    int i = p >> 5, j = p & 31;

    float in[27];
    const float* xb = x + (size_t)b * 3 * 1024;
    #pragma unroll
    for (int c = 0; c < 3; c++)
        #pragma unroll
        for (int ky = 0; ky < 3; ky++)
            #pragma unroll
            for (int kx = 0; kx < 3; kx++) {
                int yy = i - 1 + ky, xx = j - 1 + kx;
                float val = 0.f;
                if ((unsigned)yy < 32u && (unsigned)xx < 32u)
                    val = xb[c*1024 + yy*32 + xx];
                in[c*9 + ky*3 + kx] = val;
            }

    unsigned long long acc2[16];
    #pragma unroll
    for (int pp = 0; pp < 16; pp++) acc2[pp] = 0ull;
    #pragma unroll
    for (int k = 0; k < 27; k++) {
        unsigned long long ind = pk2(in[k], in[k]);
        const ulonglong2* wr = (const ulonglong2*)(s_w2 + k*32);
        #pragma unroll
        for (int pq = 0; pq < 8; pq++) {
            ulonglong2 wv = wr[pq];
            fma2(acc2[pq*2    ], ind, wv.x);
            fma2(acc2[pq*2 + 1], ind, wv.y);
        }
    }
    #pragma unroll
    for (int pp = 0; pp < 16; pp++) {
        float2 a = upk2(acc2[pp]);
        int oc = pp*2;
        s_o[tid*33 + oc    ] = fmaxf(a.x * s_sc[oc]   + s_sh[oc],   0.f);
        s_o[tid*33 + oc + 1] = fmaxf(a.y * s_sc[oc+1] + s_sh[oc+1], 0.f);
    }
    __syncthreads();

    size_t base = (size_t)blockIdx.x * 256 * 32;
    for (int idx = tid; idx < 256*32; idx += 256) {
        int pp = idx >> 5, oc = idx & 31;
        out_nhwc[base + idx] = s_o[pp*33 + oc];
    }
}

// ---------------- offconv_direct: im2col-free offset conv (one image per block) ----
// For H=W=16, S=1, TILE_M=256 (the whole image). Input image is staged ONCE into
// smem as bf16 hi/lo planes (row-padded); ldmatrix row addresses come straight
// from per-position neighbor indices, so there is NO per-chunk gather/stage.
template<int C>
__global__ __launch_bounds__(256, 2) void offconv_direct(
    const float* __restrict__ feat_nhwc,
    const __nv_bfloat16* __restrict__ wph,
    const __nv_bfloat16* __restrict__ wpl,
    const float* __restrict__ bp,
    float* __restrict__ off)
{
    constexpr int H = 16, W = 16, HW = 256;
    constexpr int K  = C * 9;
    constexpr int KC = 32;
    constexpr int NCH = K / KC;
    constexpr int NPB = 40;            // padded B row (bf16), 24 used
    constexpr int PADU = C/2 + 4;      // u32 per position per plane (row pad: +8 bf16)

    extern __shared__ char smem[];
    uint32_t* s_inh = (uint32_t*)smem;                 // (HW+1) * PADU
    uint32_t* s_inl = s_inh + (HW+1)*PADU;
    int* s_ni = (int*)(s_inl + (HW+1)*PADU);           // HW*9
    __nv_bfloat16* s_wb = (__nv_bfloat16*)(s_ni + HW*9); // [2][2][KC*NPB]
    float* s_bp = (float*)(s_wb + 4*KC*NPB);           // 20

    int tid = threadIdx.x;
    int b = blockIdx.x;
    int warp = tid >> 5, lane = tid & 31;
    int tmw = warp * 32;               // FM=2: 32 rows per warp
    int lm = lane & 15, lh = lane >> 4;

    if (tid < 18) s_bp[tid] = bp[tid];

    // ---- stage input image once: fp32 -> bf16 hi/lo planes, padded rows ----
    const float* fb = feat_nhwc + (size_t)b * HW * C;
    for (int idx = tid; idx < HW*C/4; idx += 256) {
        int pos = idx / (C/4), cq = idx - pos*(C/4);
        float4 v = ((const float4*)fb)[idx];
        split4_store(s_inh + pos*PADU, s_inl + pos*PADU, cq*2,
                     make_float2(v.x, v.y), make_float2(v.z, v.w));
    }
    if (tid < PADU) {                   // zero row for OOB taps
        s_inh[HW*PADU + tid] = 0;
        s_inl[HW*PADU + tid] = 0;
    }
    // neighbor position per (t, tap): pos index or HW (zero row)
    for (int e = tid; e < HW*9; e += 256) {
        int t = e / 9, n = e - t*9;
        int i = t >> 4, j = t & 15;
        int yy = i - 1 + n/3, xx = j - 1 + (n - (n/3)*3);
        s_ni[e] = ((unsigned)yy < 16u && (unsigned)xx < 16u) ? yy*16 + xx : HW;
    }

    // B copy: cp.async GMEM -> SMEM
    auto bcopy = [&](int k0, int buf) {
        if (tid < KC*5) {
            int row = tid / 5, gq = tid - row*5;
            __nv_bfloat16* wh = s_wb + buf*(2*KC*NPB);
            __nv_bfloat16* wl = wh + KC*NPB;
            cpa16(sptr(wh + row*NPB + gq*8), wph + (size_t)(k0+row)*40 + gq*8);
            cpa16(sptr(wl + row*NPB + gq*8), wpl + (size_t)(k0+row)*40 + gq*8);
        }
        cpa_commit();
    };

    float acc[2][3][4];
    #pragma unroll
    for (int f = 0; f < 2; f++)
        #pragma unroll
        for (int q = 0; q < 3; q++)
            #pragma unroll
            for (int r = 0; r < 4; r++) acc[f][q][r] = 0.f;

    uint32_t inh_s = sptr(s_inh), inl_s = sptr(s_inl);
    uint32_t bab = (lm*NPB + lh*8) * 2;

    bcopy(0, 0);
    cpa_wait0();
    __syncthreads();

    int ni0 = 0, ni1 = 0;   // neighbor pos for this lane's two fragment rows
    for (int i = 0; i < NCH; i++) {
        int cur = i & 1;
        if (i + 1 < NCH) bcopy((i+1)*KC, cur ^ 1);
        int k0 = i*KC;
        int n  = k0 / C, c0 = k0 - n*C;
        if (c0 == 0) {       // tap changed: refresh per-lane neighbor rows
            ni0 = s_ni[(tmw      + lm)*9 + n];
            ni1 = s_ni[(tmw + 16 + lm)*9 + n];
        }
        uint32_t wh_s = sptr(s_wb + cur*(2*KC*NPB));
        uint32_t wl_s = wh_s + KC*NPB*2;
        #pragma unroll
        for (int step = 0; step < 2; step++) {
            uint32_t co2 = (uint32_t)(c0 + step*16 + lh*8) * 2;   // byte offset in row
            uint32_t a0off = (uint32_t)ni0 * (PADU*4) + co2;
            uint32_t a1off = (uint32_t)ni1 * (PADU*4) + co2;
            uint32_t ah[2][4], al[2][4];
            ldsm4(ah[0][0], ah[0][1], ah[0][2], ah[0][3], inh_s + a0off);
            ldsm4(al[0][0], al[0][1], al[0][2], al[0][3], inl_s + a0off);
            ldsm4(ah[1][0], ah[1][1], ah[1][2], ah[1][3], inh_s + a1off);
            ldsm4(al[1][0], al[1][1], al[1][2], al[1][3], inl_s + a1off);
            uint32_t koffB = (uint32_t)(step*16*NPB*2);
            #pragma unroll
            for (int q16 = 0; q16 < 2; q16++) {
                uint32_t boff = bab + koffB + (uint32_t)(q16*16*2);
                uint32_t bh[4], bl[4];
                ldsm4t(bh[0], bh[1], bh[2], bh[3], wh_s + boff);
                ldsm4t(bl[0], bl[1], bl[2], bl[3], wl_s + boff);
                int jmax = (q16 == 0) ? 2 : 1;   // cols 24+ are zero pad
                for (int j = 0; j < jmax; j++) {
                    #pragma unroll
                    for (int f = 0; f < 2; f++) {
                        float* d = acc[f][q16*2 + j];
                        mma16816(d, ah[f], bh[j*2], bh[j*2+1]);
                        mma16816(d, ah[f], bl[j*2], bl[j*2+1]);
                        mma16816(d, al[f], bh[j*2], bh[j*2+1]);
                    }
                }
            }
        }
        cpa_wait0();
        __syncthreads();
    }

    // epilogue: add bias, store (pos, 18)
    int lq = lane >> 2, lr = lane & 3;
    #pragma unroll
    for (int f = 0; f < 2; f++) {
        #pragma unroll
        for (int q = 0; q < 3; q++) {
            int col = q*8 + lr*2;
            if (col < 18) {
                float b0 = s_bp[col], b1 = s_bp[col+1];
                int row0 = b*HW + tmw + f*16 + lq;
                int row1 = row0 + 8;
                float2 r0 = make_float2(acc[f][q][0] + b0, acc[f][q][1] + b1);
                float2 r1 = make_float2(acc[f][q][2] + b0, acc[f][q][3] + b1);
                *(float2*)(off + (size_t)row0*18 + col) = r0;
                *(float2*)(off + (size_t)row1*18 + col) = r1;
            }
        }
    }
}

// ---------------- offconv_tc: 3x3 conv C->18 as bf16x3 tensor GEMM ----------------
// (used for L2 and L4) Distance-2 gather pipeline; B via cp.async.
template<int C, int S, int H, int W, int FM, int MB>
__global__ __launch_bounds__(256, MB) void offconv_tc(
    const float* __restrict__ feat_nhwc,
    const __nv_bfloat16* __restrict__ wph,
    const __nv_bfloat16* __restrict__ wpl,
    const float* __restrict__ bp,
    float* __restrict__ off)
{
    constexpr int K  = C * 9;
    constexpr int KC = 32;
    constexpr int NCH = K / KC;
    constexpr int TILE_M = 128 * FM;
    constexpr int ITEMS = TILE_M * 8 / 256;
    constexpr int KP = 40;
    constexpr int NPB = 40;
    constexpr int h  = (H - 1) / S + 1;
    constexpr int w  = (W - 1) / S + 1;
    constexpr int HW = h * w;

    extern __shared__ char smem[];
    int* s_ni = (int*)smem;
    uint32_t* s_xa = (uint32_t*)(s_ni + TILE_M*9);
    __nv_bfloat16* s_wb = (__nv_bfloat16*)(s_xa + 4*TILE_M*20);
    float* s_bp = (float*)(s_wb + 4*KC*NPB);

    int tid = threadIdx.x;
    int gbase = blockIdx.x * TILE_M;
    int warp = tid >> 5, lane = tid & 31;
    int tmw = warp * 16 * FM;
    int lm = lane & 15, lh = lane >> 4;

    if (tid < 18) s_bp[tid] = bp[tid];

    for (int e = tid; e < TILE_M*9; e += 256) {
        int t = e / 9, n = e - t*9;
        int gpos = gbase + t;
        int b = gpos / HW, p = gpos - b*HW;
        int i = p / w, j = p - i*w;
        int yy = i*S - 1 + n/3, xx = j*S - 1 + (n - (n/3)*3);
        s_ni[e] = ((unsigned)yy < (unsigned)H && (unsigned)xx < (unsigned)W)
                  ? b*H*W*C + (yy*W + xx)*C : -1;
    }
    __syncthreads();

    auto oload = [&](int n, int c0, int idx, float4& v) {
        int t = idx >> 3, cc4 = idx & 7;
        int ix = s_ni[t*9 + n];
        v = make_float4(0.f, 0.f, 0.f, 0.f);
        if (ix >= 0) v = *(const float4*)(feat_nhwc + ix + c0 + cc4*4);
    };
    auto ostore = [&](int buf, int idx, const float4& v) {
        int t = idx >> 3, cc4 = idx & 7;
        uint32_t* xh = s_xa + buf*(2*TILE_M*20);
        uint32_t* xl = xh + TILE_M*20;
        split4_store(xh, xl, t*20 + cc4*2,
                     make_float2(v.x, v.y), make_float2(v.z, v.w));
    };
    auto bcopy = [&](int k0, int buf) {
        if (tid < KC*5) {
            int row = tid / 5, gq = tid - row*5;
            __nv_bfloat16* wh = s_wb + buf*(2*KC*NPB);
            __nv_bfloat16* wl = wh + KC*NPB;
            cpa16(sptr(wh + row*NPB + gq*8), wph + (size_t)(k0+row)*40 + gq*8);
            cpa16(sptr(wl + row*NPB + gq*8), wpl + (size_t)(k0+row)*40 + gq*8);
        }
        cpa_commit();
    };

    float acc[FM][3][4];
    #pragma unroll
    for (int f = 0; f < FM; f++)
        #pragma unroll
        for (int q = 0; q < 3; q++)
            #pragma unroll
            for (int r = 0; r < 4; r++) acc[f][q][r] = 0.f;

    uint32_t aab = ((tmw + lm)*KP + lh*8) * 2;
    uint32_t bab = (lm*NPB + lh*8) * 2;

    auto mma_step = [&](int cur, int step) {
        uint32_t xh_s = sptr(s_xa + cur*(2*TILE_M*20));
        uint32_t xl_s = xh_s + TILE_M*20*4;
        uint32_t wh_s = sptr(s_wb + cur*(2*KC*NPB));
        uint32_t wl_s = wh_s + KC*NPB*2;
        uint32_t koffA = (uint32_t)(step*16*2);
        uint32_t koffB = (uint32_t)(step*16*NPB*2);
        uint32_t ah[FM][4], al[FM][4];
        #pragma unroll
        for (int f = 0; f < FM; f++) {
            uint32_t aoff = aab + (uint32_t)(f*16*KP*2) + koffA;
            ldsm4(ah[f][0], ah[f][1], ah[f][2], ah[f][3], xh_s + aoff);
            ldsm4(al[f][0], al[f][1], al[f][2], al[f][3], xl_s + aoff);
        }
        #pragma unroll
        for (int q16 = 0; q16 < 2; q16++) {
            uint32_t boff = bab + koffB + (uint32_t)(q16*16*2);
            uint32_t bh[4], bl[4];
            ldsm4t(bh[0], bh[1], bh[2], bh[3], wh_s + boff);
            ldsm4t(bl[0], bl[1], bl[2], bl[3], wl_s + boff);
            int jmax = (q16 == 0) ? 2 : 1;
            for (int j = 0; j < jmax; j++) {
                #pragma unroll
                for (int f = 0; f < FM; f++) {
                    float* d = acc[f][q16*2 + j];
                    mma16816(d, ah[f], bh[j*2], bh[j*2+1]);
                    mma16816(d, ah[f], bl[j*2], bl[j*2+1]);
                    mma16816(d, al[f], bh[j*2], bh[j*2+1]);
                }
            }
        }
    };

    float4 hv[ITEMS];
    {
        float4 v;
        #pragma unroll
        for (int u = 0; u < ITEMS; u++) {
            oload(0, 0, tid + u*256, v);
            ostore(0, tid + u*256, v);
        }
        bcopy(0, 0);
        if (NCH > 1) {
            int n1 = KC / C, c01 = KC - n1*C;
            #pragma unroll
            for (int u = 0; u < ITEMS; u++) oload(n1, c01, tid + u*256, hv[u]);
        }
        cpa_wait0();
    }
    __syncthreads();

    for (int i = 0; i < NCH; i++) {
        int cur = i & 1, nxt = cur ^ 1;
        if (i + 1 < NCH) {
            #pragma unroll
            for (int u = 0; u < ITEMS; u++) ostore(nxt, tid + u*256, hv[u]);
            bcopy((i+1)*KC, nxt);
        }
        if (i + 2 < NCH) {
            int k2 = (i+2)*KC;
            int n2 = k2 / C, c02 = k2 - n2*C;
            #pragma unroll
            for (int u = 0; u < ITEMS; u++) oload(n2, c02, tid + u*256, hv[u]);
        }
        mma_step(cur, 0);
        mma_step(cur, 1);
        cpa_wait0();
        __syncthreads();
    }

    int lq = lane >> 2, lr = lane & 3;
    #pragma unroll
    for (int f = 0; f < FM; f++) {
        #pragma unroll
        for (int q = 0; q < 3; q++) {
            int col = q*8 + lr*2;
            if (col < 18) {
                float b0 = s_bp[col], b1 = s_bp[col+1];
                int row0 = gbase + tmw + f*16 + lq;
                int row1 = row0 + 8;
                float2 r0 = make_float2(acc[f][q][0] + b0, acc[f][q][1] + b1);
                float2 r1 = make_float2(acc[f][q][2] + b0, acc[f][q][3] + b1);
                *(float2*)(off + (size_t)row0*18 + col) = r0;
                *(float2*)(off + (size_t)row1*18 + col) = r1;
            }
        }
    }
}

// ---------------- deform: distance-2 gather pipeline + cp.async B + bf16x3 mma ----
template<int C, int O, int S, int H, int W, int TILE_M, int WM, int WN, int MB>
__global__ __launch_bounds__(256, MB) void deform_v11(
    const float* __restrict__ feat_nhwc,
    const float* __restrict__ off,
    const __nv_bfloat16* __restrict__ wth,
    const __nv_bfloat16* __restrict__ wtl,
    const float* __restrict__ g, const float* __restrict__ be,
    const float* __restrict__ m, const float* __restrict__ v,
    float* __restrict__ out_nhwc)
{
    constexpr int K    = C * 9;
    constexpr int KC   = 32;
    constexpr int NCH  = K / KC;
    constexpr int KP   = 40;
    constexpr int NP   = O + 8;
    constexpr int NWC  = O / WN;
    constexpr int QMAX = NWC / 16;
    constexpr int QN   = NWC / 8;
    constexpr int GPR  = O / 8;
    constexpr int BIT  = (KC*GPR) / 256;
    constexpr int h    = (H - 1) / S + 1;
    constexpr int w    = (W - 1) / S + 1;
    constexpr int HW   = h * w;
    static_assert(WM * WN == 8 && TILE_M == WM * 16, "warp map");
    static_assert(TILE_M * 8 == 512, "2 gather items per thread");

    extern __shared__ char smem[];
    float* s_mg = (float*)smem;
    int*   s_mi = (int*)(s_mg + TILE_M*9*4);
    uint32_t* s_xa = (uint32_t*)(s_mi + TILE_M*9*4);
    __nv_bfloat16* s_wb = (__nv_bfloat16*)(s_xa + 4*TILE_M*20);
    float* s_sc = (float*)(s_wb + 4*KC*NP);
    float* s_sh = s_sc + O;

    int tid = threadIdx.x;
    int gbase = blockIdx.x * TILE_M;
    int warp = tid >> 5, lane = tid & 31;
    int warpM = warp % WM, warpN = warp / WM;
    int tmw = warpM * 16;
    int to0 = warpN * NWC;
    int lm = lane & 15, lh = lane >> 4;

    if (tid < O) {
        float s = g[tid] / sqrtf(v[tid] + 1e-5f);
        s_sc[tid] = s;
        s_sh[tid] = be[tid] - m[tid]*s;
    }

    for (int e = tid; e < TILE_M*9; e += 256) {
        int t = e / 9, n = e - t*9;
        int gpos = gbase + t;
        int b = gpos / HW, p = gpos - b*HW;
        int i = p / w, j = p - i*w;
        float offx = off[(size_t)gpos*18 + n];
        float offy = off[(size_t)gpos*18 + 9 + n];
        float px = (float)(i*S + (n/3)) + offx;
        float py = (float)(j*S + (n - (n/3)*3)) + offy;
        const float HB = (float)(H + 1), WB = (float)(W + 1);
        float qx0 = floorf(px);
        float fx0 = fminf(fmaxf(qx0,       0.f), HB);
        float fx1 = fminf(fmaxf(qx0 + 1.f, 0.f), HB);
        float pxc = fminf(fmaxf(px,        0.f), HB);
        float qy0 = floorf(py);
        float fy0 = fminf(fmaxf(qy0,       0.f), WB);
        float fy1 = fminf(fmaxf(qy0 + 1.f, 0.f), WB);
        float pyc = fminf(fmaxf(py,        0.f), WB);
        float glt = (1.f + (fx0 - pxc)) * (1.f + (fy0 - pyc));
        float grb = (1.f - (fx1 - pxc)) * (1.f - (fy1 - pyc));
        float glb = (1.f + (fx0 - pxc)) * (1.f - (fy1 - pyc));
        float grt = (1.f - (fx1 - pxc)) * (1.f + (fy0 - pyc));
        int x0 = (int)fx0, x1 = (int)fx1, y0 = (int)fy0, y1 = (int)fy1;
        bool bx0 = (x0 >= 1 && x0 <= H), bx1 = (x1 >= 1 && x1 <= H);
        bool by0 = (y0 >= 1 && y0 <= W), by1 = (y1 >= 1 && y1 <= W);
        int base = b * H * W * C;
        s_mg[e*4+0] = (bx0 && by0) ? glt : 0.f;
        s_mg[e*4+1] = (bx1 && by1) ? grb : 0.f;
        s_mg[e*4+2] = (bx0 && by1) ? glb : 0.f;
        s_mg[e*4+3] = (bx1 && by0) ? grt : 0.f;
        s_mi[e*4+0] = (bx0 && by0) ? base + ((x0-1)*W + (y0-1))*C : 0;
        s_mi[e*4+1] = (bx1 && by1) ? base + ((x1-1)*W + (y1-1))*C : 0;
        s_mi[e*4+2] = (bx0 && by1) ? base + ((x0-1)*W + (y1-1))*C : 0;
        s_mi[e*4+3] = (bx1 && by0) ? base + ((x1-1)*W + (y0-1))*C : 0;
    }
    __syncthreads();

    struct GD { ulonglong2 a0, a1, a2, a3; };
    auto gload = [&](int n, int c0, int idx, GD& d) {
        int t = idx >> 3, cc4 = idx & 7;
        int c = c0 + cc4*4;
        const int4 i4 = *(const int4*)(s_mi + (t*9+n)*4);
        d.a0 = *(const ulonglong2*)(feat_nhwc + i4.x + c);
        d.a1 = *(const ulonglong2*)(feat_nhwc + i4.y + c);
        d.a2 = *(const ulonglong2*)(feat_nhwc + i4.z + c);
        d.a3 = *(const ulonglong2*)(feat_nhwc + i4.w + c);
    };
    auto gstore = [&](int n, int buf, int idx, const GD& d) {
        int t = idx >> 3, cc4 = idx & 7;
        uint32_t* xh = s_xa + buf*(2*TILE_M*20);
        uint32_t* xl = xh + TILE_M*20;
        const float4 g4 = *(const float4*)(s_mg + (t*9+n)*4);
        unsigned long long gx = pk2(g4.x, g4.x), gy = pk2(g4.y, g4.y);
        unsigned long long gz = pk2(g4.z, g4.z), gw = pk2(g4.w, g4.w);
        unsigned long long s01 = 0ull, s23 = 0ull;
        fma2(s01, gx, d.a0.x); fma2(s23, gx, d.a0.y);
        fma2(s01, gy, d.a1.x); fma2(s23, gy, d.a1.y);
        fma2(s01, gz, d.a2.x); fma2(s23, gz, d.a2.y);
        fma2(s01, gw, d.a3.x); fma2(s23, gw, d.a3.y);
        split4_store(xh, xl, t*20 + cc4*2, upk2(s01), upk2(s23));
    };
    auto bcopy = [&](int k0, int buf) {
        __nv_bfloat16* wh = s_wb + buf*(2*KC*NP);
        __nv_bfloat16* wl = wh + KC*NP;
        #pragma unroll
        for (int ii = 0; ii < BIT; ii++) {
            int idx = tid + ii*256;
            int row = idx / GPR, gq = idx - row*GPR;
            cpa16(sptr(wh + row*NP + gq*8), wth + (size_t)(k0+row)*O + gq*8);
            cpa16(sptr(wl + row*NP + gq*8), wtl + (size_t)(k0+row)*O + gq*8);
        }
        cpa_commit();
    };

    float acc[QN][4];
    #pragma unroll
    for (int q = 0; q < QN; q++)
        #pragma unroll
        for (int r = 0; r < 4; r++) acc[q][r] = 0.f;

    uint32_t aab = ((tmw + lm)*KP + lh*8) * 2;
    uint32_t bab = (lm*NP + to0 + lh*8) * 2;

    auto mma_step = [&](int cur, int step) {
        uint32_t xh_s = sptr(s_xa + cur*(2*TILE_M*20));
        uint32_t xl_s = xh_s + TILE_M*20*4;
        uint32_t wh_s = sptr(s_wb + cur*(2*KC*NP));
        uint32_t wl_s = wh_s + KC*NP*2;
        uint32_t koffA = (uint32_t)(step*16*2);
        uint32_t koffB = (uint32_t)(step*16*NP*2);
        uint32_t ah[4], al[4];
        ldsm4(ah[0], ah[1], ah[2], ah[3], xh_s + aab + koffA);
        ldsm4(al[0], al[1], al[2], al[3], xl_s + aab + koffA);
        #pragma unroll
        for (int q16 = 0; q16 < QMAX; q16++) {
            uint32_t boff = bab + koffB + (uint32_t)(q16*16*2);
            uint32_t bh[4], bl[4];
            ldsm4t(bh[0], bh[1], bh[2], bh[3], wh_s + boff);
            ldsm4t(bl[0], bl[1], bl[2], bl[3], wl_s + boff);
            #pragma unroll
            for (int j = 0; j < 2; j++) {
                float* d = acc[q16*2 + j];
                mma16816(d, ah, bh[j*2], bh[j*2+1]);
                mma16816(d, ah, bl[j*2], bl[j*2+1]);
                mma16816(d, al, bh[j*2], bh[j*2+1]);
            }
        }
    };

    GD hA0, hA1;
    {
        GD d;
        gload(0, 0, tid, d);       gstore(0, 0, tid, d);
        gload(0, 0, tid+256, d);   gstore(0, 0, tid+256, d);
        bcopy(0, 0);
        if (NCH > 1) {
            int n1 = KC / C, c01 = KC - n1*C;
            gload(n1, c01, tid, hA0);
            gload(n1, c01, tid+256, hA1);
        }
        cpa_wait0();
    }
    __syncthreads();

    for (int i = 0; i < NCH; i++) {
        int cur = i & 1, nxt = cur ^ 1;
        if (i + 1 < NCH) {
            int k1 = (i+1)*KC;
            int n1 = k1 / C;
            gstore(n1, nxt, tid, hA0);
            gstore(n1, nxt, tid+256, hA1);
            bcopy(k1, nxt);
        }
        if (i + 2 < NCH) {
            int k2 = (i+2)*KC;
            int n2 = k2 / C, c02 = k2 - n2*C;
            gload(n2, c02, tid, hA0);
            gload(n2, c02, tid+256, hA1);
        }
        mma_step(cur, 0);
        mma_step(cur, 1);
        cpa_wait0();
        __syncthreads();
    }

    int lq = lane >> 2, lr = lane & 3;
    #pragma unroll
    for (int q = 0; q < QN; q++) {
        int col = to0 + q*8 + lr*2;
        float sc0 = s_sc[col], sc1 = s_sc[col+1];
        float sh0 = s_sh[col], sh1 = s_sh[col+1];
        int row0 = gbase + tmw + lq;
        int row1 = row0 + 8;
        float2 r0, r1;
        r0.x = fmaxf(acc[q][0]*sc0 + sh0, 0.f);
        r0.y = fmaxf(acc[q][1]*sc1 + sh1, 0.f);
        r1.x = fmaxf(acc[q][2]*sc0 + sh0, 0.f);
        r1.y = fmaxf(acc[q][3]*sc1 + sh1, 0.f);
        *(float2*)(out_nhwc + (size_t)row0*O + col) = r0;
        *(float2*)(out_nhwc + (size_t)row1*O + col) = r1;
    }
}

// ---------------- global avg pool (8x8, NHWC) + FC (128 -> 100) ----------------
__global__ __launch_bounds__(128) void poolfc_kernel(
    const float* __restrict__ h4n,
    const float* __restrict__ wcls, const float* __restrict__ bcls,
    float* __restrict__ out)
{
    __shared__ float s_p[128];
    int b = blockIdx.x, tid = threadIdx.x;
    const float* hb = h4n + (size_t)b * 64 * 128 + tid;
    float s = 0.f;
    #pragma unroll
    for (int k = 0; k < 64; k++) s += hb[k*128];
    s_p[tid] = s * (1.f / 64.f);
    __syncthreads();
    if (tid < 100) {
        float a = bcls[tid];
        const float* wr = wcls + tid*128;
        #pragma unroll 16
        for (int o = 0; o < 128; o++) a += s_p[o] * wr[o];
        out[b*100 + tid] = a;
    }
}

// ---------------- launch ----------------
extern "C" void kernel_launch(void* const* d_in, const int* in_sizes, int n_in,
                              void* d_out, int out_size)
{
    (void)in_sizes; (void)n_in; (void)out_size;
    const float* x    = (const float*)d_in[0];
    const float* w1   = (const float*)d_in[1];
    const float* b1   = (const float*)d_in[2];
    const float* g1   = (const float*)d_in[3];
    const float* be1  = (const float*)d_in[4];
    const float* m1   = (const float*)d_in[5];
    const float* v1   = (const float*)d_in[6];
    const float* wp2  = (const float*)d_in[7];
    const float* bp2  = (const float*)d_in[8];
    const float* wc2  = (const float*)d_in[9];
    const float* g2   = (const float*)d_in[10];
    const float* be2  = (const float*)d_in[11];
    const float* m2   = (const float*)d_in[12];
    const float* v2   = (const float*)d_in[13];
    const float* wp3  = (const float*)d_in[14];
    const float* bp3  = (const float*)d_in[15];
    const float* wc3  = (const float*)d_in[16];
    const float* g3   = (const float*)d_in[17];
    const float* be3  = (const float*)d_in[18];
    const float* m3   = (const float*)d_in[19];
    const float* v3   = (const float*)d_in[20];
    const float* wp4  = (const float*)d_in[21];
    const float* bp4  = (const float*)d_in[22];
    const float* wc4  = (const float*)d_in[23];
    const float* g4   = (const float*)d_in[24];
    const float* be4  = (const float*)d_in[25];
    const float* m4   = (const float*)d_in[26];
    const float* v4   = (const float*)d_in[27];
    const float* wcls = (const float*)d_in[28];
    const float* bcls = (const float*)d_in[29];
    float* out = (float*)d_out;

    float *h1n, *off2, *h2n, *off3, *h3n, *off4, *h4n;
    __nv_bfloat16 *wth2, *wtl2, *wth3, *wtl3, *wth4, *wtl4;
    __nv_bfloat16 *wph2, *wpl2, *wph3, *wpl3, *wph4, *wpl4;
    cudaGetSymbolAddress((void**)&h1n, g_h1n);
    cudaGetSymbolAddress((void**)&off2,g_off2);
    cudaGetSymbolAddress((void**)&h2n, g_h2n);
    cudaGetSymbolAddress((void**)&off3,g_off3);
    cudaGetSymbolAddress((void**)&h3n, g_h3n);
    cudaGetSymbolAddress((void**)&off4,g_off4);
    cudaGetSymbolAddress((void**)&h4n, g_h4n);
    cudaGetSymbolAddress((void**)&wth2, g_wth2);
    cudaGetSymbolAddress((void**)&wtl2, g_wtl2);
    cudaGetSymbolAddress((void**)&wth3, g_wth3);
    cudaGetSymbolAddress((void**)&wtl3, g_wtl3);
    cudaGetSymbolAddress((void**)&wth4, g_wth4);
    cudaGetSymbolAddress((void**)&wtl4, g_wtl4);
    cudaGetSymbolAddress((void**)&wph2, g_wph2);
    cudaGetSymbolAddress((void**)&wpl2, g_wpl2);
    cudaGetSymbolAddress((void**)&wph3, g_wph3);
    cudaGetSymbolAddress((void**)&wpl3, g_wpl3);
    cudaGetSymbolAddress((void**)&wph4, g_wph4);
    cudaGetSymbolAddress((void**)&wpl4, g_wpl4);

    // head: conv1 + all weight preps in one launch
    head_kernel<<<NB*1024/256 + 1251, 256>>>(
        x, w1, b1, g1, be1, m1, v1, h1n,
        wc2, wc3, wc4, wp2, wp3, wp4,
        wth2, wtl2, wth3, wtl3, wth4, wtl4,
        wph2, wpl2, wph3, wpl3, wph4, wpl4);

    auto off_dsm = [](int TM) {
        return (size_t)TM*9*4 + (size_t)4*TM*20*4 + (size_t)4*32*40*2 + 80;
    };
    auto def_dsm = [](int TM, int O) {
        return (size_t)TM*9*4*8 + (size_t)4*TM*20*4 + (size_t)4*32*(O+8)*2
             + (size_t)O*8;
    };

    // L2: 32 -> 64, stride 2 (32x32 -> 16x16)
    {
        size_t osm = off_dsm(256);
        cudaFuncSetAttribute(offconv_tc<32,2,32,32,2,2>,
                             cudaFuncAttributeMaxDynamicSharedMemorySize, (int)osm);
        offconv_tc<32,2,32,32,2,2><<<NB*256/256, 256, osm>>>(h1n, wph2, wpl2, bp2, off2);
        size_t dsm = def_dsm(64, 64);
        cudaFuncSetAttribute(deform_v11<32,64,2,32,32,64,4,2,2>,
                             cudaFuncAttributeMaxDynamicSharedMemorySize, (int)dsm);
        deform_v11<32,64,2,32,32,64,4,2,2><<<NB*256/64, 256, dsm>>>(
            h1n, off2, wth2, wtl2, g2, be2, m2, v2, h2n);
    }
    // L3: 64 -> 128, stride 1 (16x16) — direct-ldsm offconv
    {
        constexpr int PADU = 64/2 + 4;   // 36 u32 per pos per plane
        size_t osm = (size_t)2*(257*PADU*4) + 256*9*4 + 4*32*40*2 + 80;
        cudaFuncSetAttribute(offconv_direct<64>,
                             cudaFuncAttributeMaxDynamicSharedMemorySize, (int)osm);
        offconv_direct<64><<<NB, 256, osm>>>(h2n, wph3, wpl3, bp3, off3);
        size_t dsm = def_dsm(64, 128);
        cudaFuncSetAttribute(deform_v11<64,128,1,16,16,64,4,2,2>,
                             cudaFuncAttributeMaxDynamicSharedMemorySize, (int)dsm);
        deform_v11<64,128,1,16,16,64,4,2,2><<<NB*256/64, 256, dsm>>>(
            h2n, off3, wth3, wtl3, g3, be3, m3, v3, h3n);
    }
    // L4: 128 -> 128, stride 2 (16x16 -> 8x8)
    {
        size_t osm = off_dsm(128);
        cudaFuncSetAttribute(offconv_tc<128,2,16,16,1,3>,
                             cudaFuncAttributeMaxDynamicSharedMemorySize, (int)osm);
        offconv_tc<128,2,16,16,1,3><<<NB*64/128, 256, osm>>>(h3n, wph4, wpl4, bp4, off4);
        size_t dsm = def_dsm(64, 128);
        cudaFuncSetAttribute(deform_v11<128,128,2,16,16,64,4,2,2>,
                             cudaFuncAttributeMaxDynamicSharedMemorySize, (int)dsm);
        deform_v11<128,128,2,16,16,64,4,2,2><<<NB*64/64, 256, dsm>>>(
            h3n, off4, wth4, wtl4, g4, be4, m4, v4, h4n);
    }
    // pool + FC
    poolfc_kernel<<<NB, 128>>>(h4n, wcls, bcls, out);
}